// round 1
// baseline (speedup 1.0000x reference)
#include <cuda_runtime.h>
#include <math.h>

#define HIDDEN 2048
#define INTER  768
#define NE     32
#define TOPK   8
#define MAXT   512
#define MAXP   (MAXT * TOPK)

// ---- scratch (device globals: no allocations allowed) ----
__device__ float g_topw[MAXP];
__device__ int   g_topi[MAXP];
__device__ int   g_cnt[NE];
__device__ int   g_off[NE];
__device__ int   g_pt[MAXP];    // packed pair -> token id
__device__ float g_pw[MAXP];    // packed pair -> combine weight
__device__ float g_act[(size_t)MAXP * INTER];  // 12.6 MB GLU activations

// ------------------------------------------------------------------
__global__ void zero_kernel(float* __restrict__ y, int n) {
    int i = blockIdx.x * blockDim.x + threadIdx.x;
    if (i < n) y[i] = 0.f;
}

// one block per token: logits -> softmax -> top-8 -> renormalize
__global__ void router_kernel(const float* __restrict__ x,
                              const float* __restrict__ gw) {
    int t = blockIdx.x;
    __shared__ float xs[HIDDEN];
    __shared__ float logits[NE];
    int tid = threadIdx.x;                 // 128 threads
    for (int i = tid; i < HIDDEN; i += 128) xs[i] = x[(size_t)t * HIDDEN + i];
    __syncthreads();
    int warp = tid >> 5, lane = tid & 31;
    for (int e8 = 0; e8 < 8; e8++) {
        int e = warp * 8 + e8;
        const float* w = gw + (size_t)e * HIDDEN;
        float s = 0.f;
        for (int h = lane; h < HIDDEN; h += 32) s += xs[h] * w[h];
        #pragma unroll
        for (int o = 16; o; o >>= 1) s += __shfl_xor_sync(0xffffffffu, s, o);
        if (lane == 0) logits[e] = s;
    }
    __syncthreads();
    if (tid == 0) {
        float mx = -1e30f;
        for (int e = 0; e < NE; e++) mx = fmaxf(mx, logits[e]);
        float p[NE];
        for (int e = 0; e < NE; e++) p[e] = expf(logits[e] - mx);
        // softmax denominator cancels in top-k renormalization
        bool used[NE] = {};
        float wsum = 0.f; int idx[TOPK]; float wv[TOPK];
        for (int k = 0; k < TOPK; k++) {
            float best = -1.f; int bi = 0;
            for (int e = 0; e < NE; e++)
                if (!used[e] && p[e] > best) { best = p[e]; bi = e; }
            used[bi] = true; idx[k] = bi; wv[k] = best; wsum += best;
        }
        float inv = 1.f / wsum;
        for (int k = 0; k < TOPK; k++) {
            g_topi[t * TOPK + k] = idx[k];
            g_topw[t * TOPK + k] = wv[k] * inv;
        }
    }
}

// deterministic per-expert token-list build (1 block, 32 threads)
__global__ void build_kernel(int T) {
    __shared__ int cnts[NE];
    int e = threadIdx.x;
    int np = T * TOPK;
    int c = 0;
    for (int p = 0; p < np; p++) if (g_topi[p] == e) c++;
    cnts[e] = c;
    __syncthreads();
    int off = 0;
    for (int i = 0; i < e; i++) off += cnts[i];
    g_off[e] = off;
    g_cnt[e] = c;
    int j = off;
    for (int p = 0; p < np; p++)
        if (g_topi[p] == e) { g_pt[j] = p >> 3; g_pw[j] = g_topw[p]; j++; }
}

// ------------------------------------------------------------------
// E1: act[pair][INTER] = silu(X @ Wg) * (X @ Wu), grouped by expert
// grid: (expert, token_tile, i_tile), 256 thr, 64x64x32 tiles, 4x4 micro
__global__ __launch_bounds__(256, 2)
void e1_kernel(const float* __restrict__ x,
               const float* __restrict__ gate_proj,
               const float* __restrict__ up_proj) {
    int e = blockIdx.x;
    int n = g_cnt[e];
    int mbase = blockIdx.y * 64;
    if (mbase >= n) return;
    int off   = g_off[e];
    int nbase = blockIdx.z * 64;

    __shared__ float Xs[64][33];
    __shared__ float Wg[32][64];
    __shared__ float Wu[32][64];
    __shared__ int   toks[64];

    int tid = threadIdx.x;
    if (tid < 64) {
        int m = mbase + tid;
        toks[tid] = (m < n) ? g_pt[off + m] : -1;
    }
    int tx = tid & 15, ty = tid >> 4;
    float accg[4][4] = {}, accu[4][4] = {};

    const float* gp = gate_proj + (size_t)e * HIDDEN * INTER;
    const float* up = up_proj   + (size_t)e * HIDDEN * INTER;

    for (int k0 = 0; k0 < HIDDEN; k0 += 32) {
        __syncthreads();
        #pragma unroll
        for (int k = 0; k < 8; k++) {
            int l = tid + k * 256;
            int r = l >> 5, c = l & 31;
            int t = toks[r];
            Xs[r][c] = (t >= 0) ? x[(size_t)t * HIDDEN + k0 + c] : 0.f;
        }
        #pragma unroll
        for (int k = 0; k < 8; k++) {
            int l = tid + k * 256;
            int r = l >> 6, c = l & 63;
            size_t gi = (size_t)(k0 + r) * INTER + nbase + c;
            Wg[r][c] = gp[gi];
            Wu[r][c] = up[gi];
        }
        __syncthreads();
        #pragma unroll
        for (int kk = 0; kk < 32; kk++) {
            float a[4], bg[4], bu[4];
            #pragma unroll
            for (int i = 0; i < 4; i++) a[i] = Xs[ty * 4 + i][kk];
            #pragma unroll
            for (int j = 0; j < 4; j++) { bg[j] = Wg[kk][tx * 4 + j]; bu[j] = Wu[kk][tx * 4 + j]; }
            #pragma unroll
            for (int i = 0; i < 4; i++)
                #pragma unroll
                for (int j = 0; j < 4; j++) {
                    accg[i][j] += a[i] * bg[j];
                    accu[i][j] += a[i] * bu[j];
                }
        }
    }
    #pragma unroll
    for (int i = 0; i < 4; i++) {
        int m = mbase + ty * 4 + i;
        if (m >= n) continue;
        float* arow = g_act + (size_t)(off + m) * INTER + nbase;
        #pragma unroll
        for (int j = 0; j < 4; j++) {
            float g = accg[i][j], u = accu[i][j];
            float s = g / (1.f + expf(-g));     // silu
            arow[tx * 4 + j] = s * u;
        }
    }
}

// ------------------------------------------------------------------
// E2: y[t] += w * (act @ Wd), grouped by expert
// grid: (expert, token_tile, h_tile)
__global__ __launch_bounds__(256, 2)
void e2_kernel(const float* __restrict__ down_proj,
               float* __restrict__ y) {
    int e = blockIdx.x;
    int n = g_cnt[e];
    int mbase = blockIdx.y * 64;
    if (mbase >= n) return;
    int off   = g_off[e];
    int nbase = blockIdx.z * 64;

    __shared__ float As[64][33];
    __shared__ float Bs[32][64];

    int tid = threadIdx.x;
    int tx = tid & 15, ty = tid >> 4;
    float acc[4][4] = {};
    const float* dp = down_proj + (size_t)e * INTER * HIDDEN;

    for (int k0 = 0; k0 < INTER; k0 += 32) {
        __syncthreads();
        #pragma unroll
        for (int k = 0; k < 8; k++) {
            int l = tid + k * 256;
            int r = l >> 5, c = l & 31;
            int m = mbase + r;
            As[r][c] = (m < n) ? g_act[(size_t)(off + m) * INTER + k0 + c] : 0.f;
        }
        #pragma unroll
        for (int k = 0; k < 8; k++) {
            int l = tid + k * 256;
            int r = l >> 6, c = l & 63;
            Bs[r][c] = dp[(size_t)(k0 + r) * HIDDEN + nbase + c];
        }
        __syncthreads();
        #pragma unroll
        for (int kk = 0; kk < 32; kk++) {
            float a[4], b[4];
            #pragma unroll
            for (int i = 0; i < 4; i++) a[i] = As[ty * 4 + i][kk];
            #pragma unroll
            for (int j = 0; j < 4; j++) b[j] = Bs[kk][tx * 4 + j];
            #pragma unroll
            for (int i = 0; i < 4; i++)
                #pragma unroll
                for (int j = 0; j < 4; j++) acc[i][j] += a[i] * b[j];
        }
    }
    #pragma unroll
    for (int i = 0; i < 4; i++) {
        int m = mbase + ty * 4 + i;
        if (m >= n) continue;
        int   t = g_pt[off + m];
        float w = g_pw[off + m];
        #pragma unroll
        for (int j = 0; j < 4; j++)
            atomicAdd(&y[(size_t)t * HIDDEN + nbase + tx * 4 + j], acc[i][j] * w);
    }
}

// ------------------------------------------------------------------
extern "C" void kernel_launch(void* const* d_in, const int* in_sizes, int n_in,
                              void* d_out, int out_size) {
    const float* x  = (const float*)d_in[0];   // hidden_states [1,T,H]
    const float* gw = (const float*)d_in[1];   // gate_w [E,H]
    const float* gp = (const float*)d_in[2];   // gate_proj [E,H,I]
    const float* up = (const float*)d_in[3];   // up_proj [E,H,I]
    const float* dp = (const float*)d_in[4];   // down_proj [E,I,H]
    float* y = (float*)d_out;

    int T = in_sizes[0] / HIDDEN;              // 512
    int nOut = T * HIDDEN;

    zero_kernel<<<(nOut + 1023) / 1024, 1024>>>(y, nOut);
    router_kernel<<<T, 128>>>(x, gw);
    build_kernel<<<1, NE>>>(T);

    dim3 g1(NE, (T + 63) / 64, INTER / 64);    // (32, 8, 12)
    e1_kernel<<<g1, 256>>>(x, gp, up);

    dim3 g2(NE, (T + 63) / 64, HIDDEN / 64);   // (32, 8, 32)
    e2_kernel<<<g2, 256>>>(dp, y);
}

// round 2
// speedup vs baseline: 1.5467x; 1.5467x over previous
#include <cuda_runtime.h>
#include <cuda_bf16.h>
#include <math.h>
#include <stdint.h>

#define HIDDEN 2048
#define INTER  768
#define NE     32
#define TOPK   8
#define MAXT   512
#define MAXP   (MAXT * TOPK)

// ---- scratch (device globals: no allocations allowed) ----
__device__ float g_topw[MAXP];
__device__ int   g_topi[MAXP];
__device__ int   g_cnt[NE];
__device__ int   g_off[NE];
__device__ int   g_pt[MAXP];
__device__ float g_pw[MAXP];
__device__ unsigned short g_act_hi[(size_t)MAXP * INTER];  // bf16 bits
__device__ unsigned short g_act_lo[(size_t)MAXP * INTER];

// ------------------------------------------------------------------
__global__ void zero_kernel(float* __restrict__ y, int n) {
    int i = blockIdx.x * blockDim.x + threadIdx.x;
    if (i < n) y[i] = 0.f;
}

// one block per token: logits -> softmax -> top-8 -> renormalize
__global__ void router_kernel(const float* __restrict__ x,
                              const float* __restrict__ gw) {
    int t = blockIdx.x;
    __shared__ float xs[HIDDEN];
    __shared__ float logits[NE];
    int tid = threadIdx.x;                 // 128 threads
    for (int i = tid; i < HIDDEN; i += 128) xs[i] = x[(size_t)t * HIDDEN + i];
    __syncthreads();
    int warp = tid >> 5, lane = tid & 31;
    for (int e8 = 0; e8 < 8; e8++) {
        int e = warp * 8 + e8;
        const float* w = gw + (size_t)e * HIDDEN;
        float s = 0.f;
        for (int h = lane; h < HIDDEN; h += 32) s += xs[h] * w[h];
        #pragma unroll
        for (int o = 16; o; o >>= 1) s += __shfl_xor_sync(0xffffffffu, s, o);
        if (lane == 0) logits[e] = s;
    }
    __syncthreads();
    if (tid == 0) {
        float mx = -1e30f;
        for (int e = 0; e < NE; e++) mx = fmaxf(mx, logits[e]);
        float p[NE];
        for (int e = 0; e < NE; e++) p[e] = expf(logits[e] - mx);
        bool used[NE] = {};
        float wsum = 0.f; int idx[TOPK]; float wv[TOPK];
        for (int k = 0; k < TOPK; k++) {
            float best = -1.f; int bi = 0;
            for (int e = 0; e < NE; e++)
                if (!used[e] && p[e] > best) { best = p[e]; bi = e; }
            used[bi] = true; idx[k] = bi; wv[k] = best; wsum += best;
        }
        float inv = 1.f / wsum;
        for (int k = 0; k < TOPK; k++) {
            g_topi[t * TOPK + k] = idx[k];
            g_topw[t * TOPK + k] = wv[k] * inv;
        }
    }
}

// deterministic per-expert token-list build (1 block, 32 threads)
__global__ void build_kernel(int T) {
    __shared__ int cnts[NE];
    int e = threadIdx.x;
    int np = T * TOPK;
    int c = 0;
    for (int p = 0; p < np; p++) if (g_topi[p] == e) c++;
    cnts[e] = c;
    __syncthreads();
    int off = 0;
    for (int i = 0; i < e; i++) off += cnts[i];
    g_off[e] = off;
    g_cnt[e] = c;
    int j = off;
    for (int p = 0; p < np; p++)
        if (g_topi[p] == e) { g_pt[j] = p >> 3; g_pw[j] = g_topw[p]; j++; }
}

// ------------------------------------------------------------------
// bf16 split helpers + mma
__device__ __forceinline__ void bsplit(float v, unsigned short& h, unsigned short& l) {
    __nv_bfloat16 hb = __float2bfloat16(v);
    float r = v - __bfloat162float(hb);
    __nv_bfloat16 lb = __float2bfloat16(r);
    h = __bfloat16_as_ushort(hb);
    l = __bfloat16_as_ushort(lb);
}

__device__ __forceinline__ void mma16816(float* c, const uint32_t* a, const uint32_t* b) {
    asm volatile(
        "mma.sync.aligned.m16n8k16.row.col.f32.bf16.bf16.f32 "
        "{%0,%1,%2,%3}, {%4,%5,%6,%7}, {%8,%9}, {%0,%1,%2,%3};"
        : "+f"(c[0]), "+f"(c[1]), "+f"(c[2]), "+f"(c[3])
        : "r"(a[0]), "r"(a[1]), "r"(a[2]), "r"(a[3]), "r"(b[0]), "r"(b[1]));
}

#define AS 40    // A smem row stride (bf16 elems), conflict-free frag reads
#define WS 144   // B smem k-pair row stride (bf16 elems), conflict-free frag reads
#define KT 32    // K tile

// ------------------------------------------------------------------
// E1: act = silu(X @ Wg) * (X @ Wu), grouped by expert; bf16x3 tensor-core
// grid (expert, m_tile64, i_tile64), 256 threads (8 warps, 2x4)
__global__ __launch_bounds__(256, 2)
void e1_kernel(const float* __restrict__ x,
               const float* __restrict__ gate_proj,
               const float* __restrict__ up_proj) {
    int e = blockIdx.x;
    int n = g_cnt[e];
    int mbase = blockIdx.y * 64;
    if (mbase >= n) return;
    int off   = g_off[e];
    int nbase = blockIdx.z * 64;

    __shared__ unsigned short Xh[64 * AS], Xl[64 * AS];
    __shared__ unsigned short Gh[16 * WS], Gl[16 * WS];
    __shared__ unsigned short Uh[16 * WS], Ul[16 * WS];
    __shared__ int toks[64];

    int tid = threadIdx.x;
    if (tid < 64) { int m = mbase + tid; toks[tid] = (m < n) ? g_pt[off + m] : -1; }
    __syncthreads();

    const float* gp = gate_proj + (size_t)e * HIDDEN * INTER + nbase;
    const float* up = up_proj   + (size_t)e * HIDDEN * INTER + nbase;

    int wid = tid >> 5, lane = tid & 31;
    int wm = wid >> 2, wn = wid & 3;
    int g = lane >> 2, tg = lane & 3;

    float accg[2][2][4] = {};
    float accu[2][2][4] = {};

    for (int k0 = 0; k0 < HIDDEN; k0 += KT) {
        __syncthreads();
        // --- stage X tile (64m x 32k fp32 -> bf16 hi/lo) ---
        #pragma unroll
        for (int q = 0; q < 2; q++) {
            int i4 = tid + q * 256;
            int m = i4 >> 3, kq = (i4 & 7) * 4;
            int t = toks[m];
            float4 v = (t >= 0) ? *(const float4*)(x + (size_t)t * HIDDEN + k0 + kq)
                                : make_float4(0.f, 0.f, 0.f, 0.f);
            float vv[4] = {v.x, v.y, v.z, v.w};
            #pragma unroll
            for (int j = 0; j < 4; j++) {
                unsigned short h, l; bsplit(vv[j], h, l);
                Xh[m * AS + kq + j] = h;
                Xl[m * AS + kq + j] = l;
            }
        }
        // --- stage Wg/Wu tiles (32k x 64n fp32 -> packed k-pair bf16 hi/lo) ---
        #pragma unroll
        for (int q = 0; q < 2; q++) {
            int i4 = tid + q * 256;
            int k = i4 >> 4, nq = (i4 & 15) * 4;
            size_t gi = (size_t)(k0 + k) * INTER + nq;
            float4 vg = *(const float4*)(gp + gi);
            float4 vu = *(const float4*)(up + gi);
            int base = (k >> 1) * WS + (k & 1);
            float vgv[4] = {vg.x, vg.y, vg.z, vg.w};
            float vuv[4] = {vu.x, vu.y, vu.z, vu.w};
            #pragma unroll
            for (int j = 0; j < 4; j++) {
                unsigned short h, l;
                bsplit(vgv[j], h, l); Gh[base + (nq + j) * 2] = h; Gl[base + (nq + j) * 2] = l;
                bsplit(vuv[j], h, l); Uh[base + (nq + j) * 2] = h; Ul[base + (nq + j) * 2] = l;
            }
        }
        __syncthreads();
        // --- compute: 2 x k16 steps ---
        #pragma unroll
        for (int kk = 0; kk < KT; kk += 16) {
            uint32_t ah[2][4], al[2][4];
            #pragma unroll
            for (int mf = 0; mf < 2; mf++) {
                int r0 = (wm * 32 + mf * 16 + g) * AS;
                int cb = kk + 2 * tg;
                ah[mf][0] = *(uint32_t*)&Xh[r0 + cb];
                ah[mf][1] = *(uint32_t*)&Xh[r0 + 8 * AS + cb];
                ah[mf][2] = *(uint32_t*)&Xh[r0 + cb + 8];
                ah[mf][3] = *(uint32_t*)&Xh[r0 + 8 * AS + cb + 8];
                al[mf][0] = *(uint32_t*)&Xl[r0 + cb];
                al[mf][1] = *(uint32_t*)&Xl[r0 + 8 * AS + cb];
                al[mf][2] = *(uint32_t*)&Xl[r0 + cb + 8];
                al[mf][3] = *(uint32_t*)&Xl[r0 + 8 * AS + cb + 8];
            }
            int kp0 = (kk + 2 * tg) >> 1;
            int kp1 = kp0 + 4;
            // gate
            {
                uint32_t bh[2][2], bl[2][2];
                #pragma unroll
                for (int nf = 0; nf < 2; nf++) {
                    int c2 = (wn * 16 + nf * 8 + g) * 2;
                    bh[nf][0] = *(uint32_t*)&Gh[kp0 * WS + c2];
                    bh[nf][1] = *(uint32_t*)&Gh[kp1 * WS + c2];
                    bl[nf][0] = *(uint32_t*)&Gl[kp0 * WS + c2];
                    bl[nf][1] = *(uint32_t*)&Gl[kp1 * WS + c2];
                }
                #pragma unroll
                for (int mf = 0; mf < 2; mf++)
                #pragma unroll
                for (int nf = 0; nf < 2; nf++) {
                    mma16816(accg[mf][nf], ah[mf], bh[nf]);
                    mma16816(accg[mf][nf], ah[mf], bl[nf]);
                    mma16816(accg[mf][nf], al[mf], bh[nf]);
                }
            }
            // up
            {
                uint32_t bh[2][2], bl[2][2];
                #pragma unroll
                for (int nf = 0; nf < 2; nf++) {
                    int c2 = (wn * 16 + nf * 8 + g) * 2;
                    bh[nf][0] = *(uint32_t*)&Uh[kp0 * WS + c2];
                    bh[nf][1] = *(uint32_t*)&Uh[kp1 * WS + c2];
                    bl[nf][0] = *(uint32_t*)&Ul[kp0 * WS + c2];
                    bl[nf][1] = *(uint32_t*)&Ul[kp1 * WS + c2];
                }
                #pragma unroll
                for (int mf = 0; mf < 2; mf++)
                #pragma unroll
                for (int nf = 0; nf < 2; nf++) {
                    mma16816(accu[mf][nf], ah[mf], bh[nf]);
                    mma16816(accu[mf][nf], ah[mf], bl[nf]);
                    mma16816(accu[mf][nf], al[mf], bh[nf]);
                }
            }
        }
    }
    // --- epilogue: silu(g)*u -> bf16 hi/lo -> g_act ---
    #pragma unroll
    for (int mf = 0; mf < 2; mf++)
    #pragma unroll
    for (int nf = 0; nf < 2; nf++)
    #pragma unroll
    for (int i = 0; i < 4; i++) {
        int m = mbase + wm * 32 + mf * 16 + g + (i >> 1) * 8;
        if (m >= n) continue;
        int col = nbase + wn * 16 + nf * 8 + 2 * tg + (i & 1);
        float gv = accg[mf][nf][i], uv = accu[mf][nf][i];
        float a = (gv / (1.f + __expf(-gv))) * uv;
        unsigned short h, l; bsplit(a, h, l);
        size_t ai = (size_t)(off + m) * INTER + col;
        g_act_hi[ai] = h;
        g_act_lo[ai] = l;
    }
}

// ------------------------------------------------------------------
// E2: y[t] += w * (act @ Wd); bf16x3 tensor-core; grid (expert, m_tile, h_tile)
__global__ __launch_bounds__(256, 2)
void e2_kernel(const float* __restrict__ down_proj,
               float* __restrict__ y) {
    int e = blockIdx.x;
    int n = g_cnt[e];
    int mbase = blockIdx.y * 64;
    if (mbase >= n) return;
    int off   = g_off[e];
    int nbase = blockIdx.z * 64;

    __shared__ unsigned short Ah[64 * AS], Al[64 * AS];
    __shared__ unsigned short Dh[16 * WS], Dl[16 * WS];

    const float* dp = down_proj + (size_t)e * INTER * HIDDEN + nbase;

    int tid = threadIdx.x;
    int wid = tid >> 5, lane = tid & 31;
    int wm = wid >> 2, wn = wid & 3;
    int g = lane >> 2, tg = lane & 3;

    float acc[2][2][4] = {};

    for (int k0 = 0; k0 < INTER; k0 += KT) {
        __syncthreads();
        // --- stage act tile (already bf16 hi/lo in global) ---
        #pragma unroll
        for (int q = 0; q < 4; q++) {
            int i2 = tid + q * 256;               // u32 index (2 bf16)
            int m = i2 >> 4, k2 = (i2 & 15) * 2;
            uint32_t vh = 0, vl = 0;
            if (mbase + m < n) {
                size_t ai = (size_t)(off + mbase + m) * INTER + k0 + k2;
                vh = *(const uint32_t*)&g_act_hi[ai];
                vl = *(const uint32_t*)&g_act_lo[ai];
            }
            *(uint32_t*)&Ah[m * AS + k2] = vh;
            *(uint32_t*)&Al[m * AS + k2] = vl;
        }
        // --- stage down tile ---
        #pragma unroll
        for (int q = 0; q < 2; q++) {
            int i4 = tid + q * 256;
            int k = i4 >> 4, nq = (i4 & 15) * 4;
            float4 v = *(const float4*)(dp + (size_t)(k0 + k) * HIDDEN + nq);
            int base = (k >> 1) * WS + (k & 1);
            float vv[4] = {v.x, v.y, v.z, v.w};
            #pragma unroll
            for (int j = 0; j < 4; j++) {
                unsigned short h, l; bsplit(vv[j], h, l);
                Dh[base + (nq + j) * 2] = h;
                Dl[base + (nq + j) * 2] = l;
            }
        }
        __syncthreads();
        #pragma unroll
        for (int kk = 0; kk < KT; kk += 16) {
            uint32_t ah[2][4], al[2][4];
            #pragma unroll
            for (int mf = 0; mf < 2; mf++) {
                int r0 = (wm * 32 + mf * 16 + g) * AS;
                int cb = kk + 2 * tg;
                ah[mf][0] = *(uint32_t*)&Ah[r0 + cb];
                ah[mf][1] = *(uint32_t*)&Ah[r0 + 8 * AS + cb];
                ah[mf][2] = *(uint32_t*)&Ah[r0 + cb + 8];
                ah[mf][3] = *(uint32_t*)&Ah[r0 + 8 * AS + cb + 8];
                al[mf][0] = *(uint32_t*)&Al[r0 + cb];
                al[mf][1] = *(uint32_t*)&Al[r0 + 8 * AS + cb];
                al[mf][2] = *(uint32_t*)&Al[r0 + cb + 8];
                al[mf][3] = *(uint32_t*)&Al[r0 + 8 * AS + cb + 8];
            }
            int kp0 = (kk + 2 * tg) >> 1;
            int kp1 = kp0 + 4;
            uint32_t bh[2][2], bl[2][2];
            #pragma unroll
            for (int nf = 0; nf < 2; nf++) {
                int c2 = (wn * 16 + nf * 8 + g) * 2;
                bh[nf][0] = *(uint32_t*)&Dh[kp0 * WS + c2];
                bh[nf][1] = *(uint32_t*)&Dh[kp1 * WS + c2];
                bl[nf][0] = *(uint32_t*)&Dl[kp0 * WS + c2];
                bl[nf][1] = *(uint32_t*)&Dl[kp1 * WS + c2];
            }
            #pragma unroll
            for (int mf = 0; mf < 2; mf++)
            #pragma unroll
            for (int nf = 0; nf < 2; nf++) {
                mma16816(acc[mf][nf], ah[mf], bh[nf]);
                mma16816(acc[mf][nf], ah[mf], bl[nf]);
                mma16816(acc[mf][nf], al[mf], bh[nf]);
            }
        }
    }
    // --- epilogue: weighted combine via red.global ---
    #pragma unroll
    for (int mf = 0; mf < 2; mf++) {
        int mrow0 = mbase + wm * 32 + mf * 16 + g;
        #pragma unroll
        for (int half = 0; half < 2; half++) {
            int m = mrow0 + half * 8;
            if (m >= n) continue;
            int   t = g_pt[off + m];
            float w = g_pw[off + m];
            #pragma unroll
            for (int nf = 0; nf < 2; nf++) {
                int col = nbase + wn * 16 + nf * 8 + 2 * tg;
                atomicAdd(&y[(size_t)t * HIDDEN + col],     acc[mf][nf][half * 2 + 0] * w);
                atomicAdd(&y[(size_t)t * HIDDEN + col + 1], acc[mf][nf][half * 2 + 1] * w);
            }
        }
    }
}

// ------------------------------------------------------------------
extern "C" void kernel_launch(void* const* d_in, const int* in_sizes, int n_in,
                              void* d_out, int out_size) {
    const float* x  = (const float*)d_in[0];   // hidden_states [1,T,H]
    const float* gw = (const float*)d_in[1];   // gate_w [E,H]
    const float* gp = (const float*)d_in[2];   // gate_proj [E,H,I]
    const float* up = (const float*)d_in[3];   // up_proj [E,H,I]
    const float* dp = (const float*)d_in[4];   // down_proj [E,I,H]
    float* y = (float*)d_out;

    int T = in_sizes[0] / HIDDEN;              // 512
    int nOut = T * HIDDEN;

    zero_kernel<<<(nOut + 1023) / 1024, 1024>>>(y, nOut);
    router_kernel<<<T, 128>>>(x, gw);
    build_kernel<<<1, NE>>>(T);

    dim3 g1(NE, (T + 63) / 64, INTER / 64);    // (32, 8, 12)
    e1_kernel<<<g1, 256>>>(x, gp, up);

    dim3 g2(NE, (T + 63) / 64, HIDDEN / 64);   // (32, 8, 32)
    e2_kernel<<<g2, 256>>>(dp, y);
}

// round 4
// speedup vs baseline: 2.1714x; 1.4039x over previous
#include <cuda_runtime.h>
#include <cuda_bf16.h>
#include <math.h>
#include <stdint.h>

#define HIDDEN 2048
#define INTER  768
#define NE     32
#define TOPK   8
#define MAXT   512
#define MAXP   (MAXT * TOPK)

typedef unsigned short ushort_t;

// ---- scratch (device globals) ----
__device__ float g_topw[MAXP];
__device__ int   g_topi[MAXP];
__device__ int   g_cnt[NE];
__device__ int   g_off[NE];
__device__ int   g_pt[MAXP];
__device__ int   g_t2p[MAXP];
__device__ ushort_t g_x_hi[(size_t)MAXT * HIDDEN];
__device__ ushort_t g_x_lo[(size_t)MAXT * HIDDEN];
__device__ ushort_t g_act_hi[(size_t)MAXP * INTER];
__device__ ushort_t g_act_lo[(size_t)MAXP * INTER];
__device__ float g_eout[(size_t)MAXP * HIDDEN];   // 33.5 MB per-pair down output

// ================= helpers =================
__device__ __forceinline__ uint32_t smem_u32(const void* p) {
    uint32_t a;
    asm("{ .reg .u64 t; cvta.to.shared.u64 t, %1; cvt.u32.u64 %0, t; }" : "=r"(a) : "l"(p));
    return a;
}
__device__ __forceinline__ void cpa16(uint32_t dst, const void* src) {
    asm volatile("cp.async.ca.shared.global [%0], [%1], 16;" :: "r"(dst), "l"(src));
}
__device__ __forceinline__ void cpa8z(uint32_t dst, const void* src, int zf) {
    asm volatile("cp.async.ca.shared.global [%0], [%1], 8, %2;" :: "r"(dst), "l"(src), "r"(zf));
}
#define CP_COMMIT() asm volatile("cp.async.commit_group;" ::: "memory")
#define CP_WAIT0()  asm volatile("cp.async.wait_group 0;" ::: "memory")

__device__ __forceinline__ unsigned short bfh(float v) { return __bfloat16_as_ushort(__float2bfloat16(v)); }
__device__ __forceinline__ float bff(unsigned short u) { return __bfloat162float(__ushort_as_bfloat16(u)); }
__device__ __forceinline__ void split2(float a, float b, uint32_t& hi, uint32_t& lo) {
    unsigned short ha = bfh(a), hb = bfh(b);
    float ra = a - bff(ha), rb = b - bff(hb);
    hi = (uint32_t)ha | ((uint32_t)hb << 16);
    lo = (uint32_t)bfh(ra) | ((uint32_t)bfh(rb) << 16);
}
__device__ __forceinline__ void mma16816(float* c, const uint32_t* a, const uint32_t* b) {
    asm volatile(
        "mma.sync.aligned.m16n8k16.row.col.f32.bf16.bf16.f32 "
        "{%0,%1,%2,%3}, {%4,%5,%6,%7}, {%8,%9}, {%0,%1,%2,%3};"
        : "+f"(c[0]), "+f"(c[1]), "+f"(c[2]), "+f"(c[3])
        : "r"(a[0]), "r"(a[1]), "r"(a[2]), "r"(a[3]), "r"(b[0]), "r"(b[1]));
}

#define AS 40    // A smem row stride (ushorts)
#define WS 144   // B smem k-pair row stride (ushorts)
#define RS 68    // raw fp32 row stride (floats)

// ================= small kernels =================
__global__ void prep_x_kernel(const float* __restrict__ x, int nTot) {
    int i = (blockIdx.x * 256 + threadIdx.x) * 4;
    if (i < nTot) {
        float4 v = *(const float4*)(x + i);
        uint2 H, L;
        split2(v.x, v.y, H.x, L.x);
        split2(v.z, v.w, H.y, L.y);
        *(uint2*)&g_x_hi[i] = H;
        *(uint2*)&g_x_lo[i] = L;
    }
}

__global__ void router_kernel(const float* __restrict__ x, const float* __restrict__ gw) {
    int t = blockIdx.x;
    __shared__ float xs[HIDDEN];
    __shared__ float logits[NE];
    int tid = threadIdx.x;
    for (int i = tid; i < HIDDEN; i += 128) xs[i] = x[(size_t)t * HIDDEN + i];
    __syncthreads();
    int warp = tid >> 5, lane = tid & 31;
    for (int e8 = 0; e8 < 8; e8++) {
        int e = warp * 8 + e8;
        const float* w = gw + (size_t)e * HIDDEN;
        float s = 0.f;
        for (int h = lane; h < HIDDEN; h += 32) s += xs[h] * w[h];
        #pragma unroll
        for (int o = 16; o; o >>= 1) s += __shfl_xor_sync(0xffffffffu, s, o);
        if (lane == 0) logits[e] = s;
    }
    __syncthreads();
    if (tid == 0) {
        float mx = -1e30f;
        for (int e = 0; e < NE; e++) mx = fmaxf(mx, logits[e]);
        float p[NE];
        for (int e = 0; e < NE; e++) p[e] = expf(logits[e] - mx);
        bool used[NE] = {};
        float wsum = 0.f; int idx[TOPK]; float wv[TOPK];
        for (int k = 0; k < TOPK; k++) {
            float best = -1.f; int bi = 0;
            for (int e = 0; e < NE; e++)
                if (!used[e] && p[e] > best) { best = p[e]; bi = e; }
            used[bi] = true; idx[k] = bi; wv[k] = best; wsum += best;
        }
        float inv = 1.f / wsum;
        for (int k = 0; k < TOPK; k++) {
            g_topi[t * TOPK + k] = idx[k];
            g_topw[t * TOPK + k] = wv[k] * inv;
        }
    }
}

__global__ void build_kernel(int T) {
    __shared__ int cnts[NE];
    int e = threadIdx.x;
    int np = T * TOPK;
    int c = 0;
    for (int p = 0; p < np; p++) if (g_topi[p] == e) c++;
    cnts[e] = c;
    __syncthreads();
    int off = 0;
    for (int i = 0; i < e; i++) off += cnts[i];
    g_off[e] = off;
    g_cnt[e] = c;
    int j = off;
    for (int p = 0; p < np; p++)
        if (g_topi[p] == e) { g_pt[j] = p >> 3; g_t2p[p] = j; j++; }
}

__global__ void combine_kernel(float* __restrict__ y) {
    int t = blockIdx.x, tid = threadIdx.x;
    __shared__ int   pj[TOPK];
    __shared__ float pw[TOPK];
    if (tid < TOPK) { pj[tid] = g_t2p[t * TOPK + tid]; pw[tid] = g_topw[t * TOPK + tid]; }
    __syncthreads();
    #pragma unroll
    for (int h = 0; h < 2; h++) {
        int c = h * 1024 + tid * 4;
        float4 acc = make_float4(0.f, 0.f, 0.f, 0.f);
        #pragma unroll
        for (int k = 0; k < TOPK; k++) {
            const float4 v = *(const float4*)(g_eout + (size_t)pj[k] * HIDDEN + c);
            float w = pw[k];
            acc.x += w * v.x; acc.y += w * v.y; acc.z += w * v.z; acc.w += w * v.w;
        }
        *(float4*)(y + (size_t)t * HIDDEN + c) = acc;
    }
}

// ================= E1 =================
// smem: toks[64] @0 (256B) | A bufs @256 (2 x (hi5120+lo5120)) | raw W @20736 (2 x (G8704+U8704))
//       | bfW @55552 (Gh,Gl,Uh,Ul x4608)
#define E1_A    256
#define E1_RAW  20736
#define E1_BFW  55552
#define E1_SMEM 73984

extern __shared__ __align__(16) char dsm[];

__device__ __forceinline__ void e1_prefetch(int tid, const int* toks, uint32_t sb,
                                            const float* gp, const float* up_,
                                            int k0, int b) {
    uint32_t Abase = sb + E1_A + b * 10240;
    #pragma unroll
    for (int q = 0; q < 2; q++) {
        int lin = q * 256 + tid;
        int m = lin >> 3, c = lin & 7;
        int t = toks[m];
        int zf = (t >= 0) ? 8 : 0;
        size_t so = (size_t)(t >= 0 ? t : 0) * HIDDEN + k0 + c * 4;
        uint32_t d = Abase + m * 80 + c * 8;
        cpa8z(d, g_x_hi + so, zf);
        cpa8z(d + 5120, g_x_lo + so, zf);
    }
    uint32_t Rbase = sb + E1_RAW + b * 17408;
    #pragma unroll
    for (int q = 0; q < 2; q++) {
        int lin = q * 256 + tid;
        int k = lin >> 4, n4 = lin & 15;
        uint32_t d = Rbase + k * 272 + n4 * 16;
        size_t so = (size_t)(k0 + k) * INTER + n4 * 4;
        cpa16(d, gp + so);
        cpa16(d + 8704, up_ + so);
    }
    CP_COMMIT();
}

__global__ __launch_bounds__(256, 2)
void e1_kernel(const float* __restrict__ gate_proj,
               const float* __restrict__ up_proj) {
    int e = blockIdx.x;
    int n = g_cnt[e];
    int mbase = blockIdx.y * 64;
    if (mbase >= n) return;
    int off = g_off[e];
    int nbase = blockIdx.z * 64;

    uint32_t sb = smem_u32(dsm);
    int tid = threadIdx.x, wid = tid >> 5, lane = tid & 31;
    int* toks = (int*)dsm;
    if (tid < 64) { int m = mbase + tid; toks[tid] = (m < n) ? g_pt[off + m] : -1; }
    __syncthreads();

    const float* gp  = gate_proj + (size_t)e * HIDDEN * INTER + nbase;
    const float* up_ = up_proj   + (size_t)e * HIDDEN * INTER + nbase;

    int wm = wid >> 2, wn = wid & 3;
    int g = lane >> 2, tg = lane & 3;

    float accg[2][2][4] = {};
    float accu[2][2][4] = {};

    ushort_t* Gh = (ushort_t*)(dsm + E1_BFW);
    ushort_t* Gl = Gh + 2304;
    ushort_t* Uh = Gh + 4608;
    ushort_t* Ul = Gh + 6912;

    e1_prefetch(tid, toks, sb, gp, up_, 0, 0);

    for (int it = 0; it < HIDDEN / 32; it++) {
        int b = it & 1;
        CP_WAIT0();
        __syncthreads();
        if (it + 1 < HIDDEN / 32)
            e1_prefetch(tid, toks, sb, gp, up_, (it + 1) * 32, b ^ 1);

        // ---- convert raw W -> split bf16 ----
        {
            const float* rawG = (const float*)(dsm + E1_RAW + b * 17408);
            const float* rawU = rawG + 2176;
            int nn = tid & 63, kg = tid >> 6;
            #pragma unroll
            for (int kp = 0; kp < 4; kp++) {
                int k = kg * 8 + kp * 2;
                int wi = (k >> 1) * WS + 2 * nn;
                uint32_t hi, lo;
                split2(rawG[k * RS + nn], rawG[(k + 1) * RS + nn], hi, lo);
                *(uint32_t*)&Gh[wi] = hi;
                *(uint32_t*)&Gl[wi] = lo;
                split2(rawU[k * RS + nn], rawU[(k + 1) * RS + nn], hi, lo);
                *(uint32_t*)&Uh[wi] = hi;
                *(uint32_t*)&Ul[wi] = lo;
            }
        }
        __syncthreads();

        const ushort_t* Xh = (const ushort_t*)(dsm + E1_A + b * 10240);
        const ushort_t* Xl = Xh + 2560;
        #pragma unroll
        for (int kk = 0; kk < 32; kk += 16) {
            uint32_t ah[2][4], al[2][4];
            #pragma unroll
            for (int mf = 0; mf < 2; mf++) {
                int r0 = (wm * 32 + mf * 16 + g) * AS;
                int cb = kk + 2 * tg;
                ah[mf][0] = *(const uint32_t*)&Xh[r0 + cb];
                ah[mf][1] = *(const uint32_t*)&Xh[r0 + 8 * AS + cb];
                ah[mf][2] = *(const uint32_t*)&Xh[r0 + cb + 8];
                ah[mf][3] = *(const uint32_t*)&Xh[r0 + 8 * AS + cb + 8];
                al[mf][0] = *(const uint32_t*)&Xl[r0 + cb];
                al[mf][1] = *(const uint32_t*)&Xl[r0 + 8 * AS + cb];
                al[mf][2] = *(const uint32_t*)&Xl[r0 + cb + 8];
                al[mf][3] = *(const uint32_t*)&Xl[r0 + 8 * AS + cb + 8];
            }
            int kp0 = (kk + 2 * tg) >> 1;
            int kp1 = kp0 + 4;
            {
                uint32_t bh[2][2], bl[2][2];
                #pragma unroll
                for (int nf = 0; nf < 2; nf++) {
                    int c2 = (wn * 16 + nf * 8 + g) * 2;
                    bh[nf][0] = *(const uint32_t*)&Gh[kp0 * WS + c2];
                    bh[nf][1] = *(const uint32_t*)&Gh[kp1 * WS + c2];
                    bl[nf][0] = *(const uint32_t*)&Gl[kp0 * WS + c2];
                    bl[nf][1] = *(const uint32_t*)&Gl[kp1 * WS + c2];
                }
                #pragma unroll
                for (int mf = 0; mf < 2; mf++)
                #pragma unroll
                for (int nf = 0; nf < 2; nf++) {
                    mma16816(accg[mf][nf], ah[mf], bh[nf]);
                    mma16816(accg[mf][nf], ah[mf], bl[nf]);
                    mma16816(accg[mf][nf], al[mf], bh[nf]);
                }
            }
            {
                uint32_t bh[2][2], bl[2][2];
                #pragma unroll
                for (int nf = 0; nf < 2; nf++) {
                    int c2 = (wn * 16 + nf * 8 + g) * 2;
                    bh[nf][0] = *(const uint32_t*)&Uh[kp0 * WS + c2];
                    bh[nf][1] = *(const uint32_t*)&Uh[kp1 * WS + c2];
                    bl[nf][0] = *(const uint32_t*)&Ul[kp0 * WS + c2];
                    bl[nf][1] = *(const uint32_t*)&Ul[kp1 * WS + c2];
                }
                #pragma unroll
                for (int mf = 0; mf < 2; mf++)
                #pragma unroll
                for (int nf = 0; nf < 2; nf++) {
                    mma16816(accu[mf][nf], ah[mf], bh[nf]);
                    mma16816(accu[mf][nf], ah[mf], bl[nf]);
                    mma16816(accu[mf][nf], al[mf], bh[nf]);
                }
            }
        }
    }

    // ---- epilogue: silu(g)*u -> split bf16 -> g_act ----
    #pragma unroll
    for (int mf = 0; mf < 2; mf++)
    #pragma unroll
    for (int nf = 0; nf < 2; nf++)
    #pragma unroll
    for (int i = 0; i < 4; i++) {
        int m = mbase + wm * 32 + mf * 16 + g + (i >> 1) * 8;
        if (m >= n) continue;
        int col = nbase + wn * 16 + nf * 8 + 2 * tg + (i & 1);
        float gv = accg[mf][nf][i], uv = accu[mf][nf][i];
        float a = (gv / (1.f + __expf(-gv))) * uv;
        unsigned short h = bfh(a);
        float r = a - bff(h);
        size_t ai = (size_t)(off + m) * INTER + col;
        g_act_hi[ai] = h;
        g_act_lo[ai] = bfh(r);
    }
}

// ================= E2 =================
// smem: A bufs @0 (2 x (hi5120+lo5120)) | raw B @20480 (2 x 8704) | bfB @37888 (Bh,Bl x4608)
#define E2_A    0
#define E2_RAW  20480
#define E2_BF   37888
#define E2_SMEM 47104

__device__ __forceinline__ void e2_prefetch(int tid, int off, int mbase, int n, uint32_t sb,
                                            const float* dp, int k0, int b) {
    uint32_t Abase = sb + E2_A + b * 10240;
    #pragma unroll
    for (int q = 0; q < 2; q++) {
        int lin = q * 256 + tid;
        int m = lin >> 3, c = lin & 7;
        bool valid = (mbase + m) < n;
        int zf = valid ? 8 : 0;
        size_t so = valid ? ((size_t)(off + mbase + m) * INTER + k0 + c * 4) : 0;
        uint32_t d = Abase + m * 80 + c * 8;
        cpa8z(d, g_act_hi + so, zf);
        cpa8z(d + 5120, g_act_lo + so, zf);
    }
    uint32_t Rbase = sb + E2_RAW + b * 8704;
    #pragma unroll
    for (int q = 0; q < 2; q++) {
        int lin = q * 256 + tid;
        int k = lin >> 4, n4 = lin & 15;
        cpa16(Rbase + k * 272 + n4 * 16, dp + (size_t)(k0 + k) * HIDDEN + n4 * 4);
    }
    CP_COMMIT();
}

__global__ __launch_bounds__(256, 2)
void e2_kernel(const float* __restrict__ down_proj) {
    int e = blockIdx.x;
    int n = g_cnt[e];
    int mbase = blockIdx.y * 64;
    if (mbase >= n) return;
    int off = g_off[e];
    int nbase = blockIdx.z * 64;

    uint32_t sb = smem_u32(dsm);
    int tid = threadIdx.x, wid = tid >> 5, lane = tid & 31;
    int wm = wid >> 2, wn = wid & 3;
    int g = lane >> 2, tg = lane & 3;

    const float* dp = down_proj + (size_t)e * INTER * HIDDEN + nbase;

    float acc[2][2][4] = {};

    ushort_t* Bh = (ushort_t*)(dsm + E2_BF);
    ushort_t* Bl = Bh + 2304;

    e2_prefetch(tid, off, mbase, n, sb, dp, 0, 0);

    for (int it = 0; it < INTER / 32; it++) {
        int b = it & 1;
        CP_WAIT0();
        __syncthreads();
        if (it + 1 < INTER / 32)
            e2_prefetch(tid, off, mbase, n, sb, dp, (it + 1) * 32, b ^ 1);

        // ---- convert raw B ----
        {
            const float* rawB = (const float*)(dsm + E2_RAW + b * 8704);
            int nn = tid & 63, kg = tid >> 6;
            #pragma unroll
            for (int kp = 0; kp < 4; kp++) {
                int k = kg * 8 + kp * 2;
                int wi = (k >> 1) * WS + 2 * nn;
                uint32_t hi, lo;
                split2(rawB[k * RS + nn], rawB[(k + 1) * RS + nn], hi, lo);
                *(uint32_t*)&Bh[wi] = hi;
                *(uint32_t*)&Bl[wi] = lo;
            }
        }
        __syncthreads();

        const ushort_t* Ahp = (const ushort_t*)(dsm + E2_A + b * 10240);
        const ushort_t* Alp = Ahp + 2560;
        #pragma unroll
        for (int kk = 0; kk < 32; kk += 16) {
            uint32_t ah[2][4], al[2][4];
            #pragma unroll
            for (int mf = 0; mf < 2; mf++) {
                int r0 = (wm * 32 + mf * 16 + g) * AS;
                int cb = kk + 2 * tg;
                ah[mf][0] = *(const uint32_t*)&Ahp[r0 + cb];
                ah[mf][1] = *(const uint32_t*)&Ahp[r0 + 8 * AS + cb];
                ah[mf][2] = *(const uint32_t*)&Ahp[r0 + cb + 8];
                ah[mf][3] = *(const uint32_t*)&Ahp[r0 + 8 * AS + cb + 8];
                al[mf][0] = *(const uint32_t*)&Alp[r0 + cb];
                al[mf][1] = *(const uint32_t*)&Alp[r0 + 8 * AS + cb];
                al[mf][2] = *(const uint32_t*)&Alp[r0 + cb + 8];
                al[mf][3] = *(const uint32_t*)&Alp[r0 + 8 * AS + cb + 8];
            }
            int kp0 = (kk + 2 * tg) >> 1;
            int kp1 = kp0 + 4;
            uint32_t bh[2][2], bl[2][2];
            #pragma unroll
            for (int nf = 0; nf < 2; nf++) {
                int c2 = (wn * 16 + nf * 8 + g) * 2;
                bh[nf][0] = *(const uint32_t*)&Bh[kp0 * WS + c2];
                bh[nf][1] = *(const uint32_t*)&Bh[kp1 * WS + c2];
                bl[nf][0] = *(const uint32_t*)&Bl[kp0 * WS + c2];
                bl[nf][1] = *(const uint32_t*)&Bl[kp1 * WS + c2];
            }
            #pragma unroll
            for (int mf = 0; mf < 2; mf++)
            #pragma unroll
            for (int nf = 0; nf < 2; nf++) {
                mma16816(acc[mf][nf], ah[mf], bh[nf]);
                mma16816(acc[mf][nf], ah[mf], bl[nf]);
                mma16816(acc[mf][nf], al[mf], bh[nf]);
            }
        }
    }

    // ---- epilogue: raw per-pair output rows (vectorized, no atomics) ----
    #pragma unroll
    for (int mf = 0; mf < 2; mf++) {
        #pragma unroll
        for (int half = 0; half < 2; half++) {
            int m = mbase + wm * 32 + mf * 16 + g + half * 8;
            if (m >= n) continue;
            float* orow = g_eout + (size_t)(off + m) * HIDDEN + nbase;
            #pragma unroll
            for (int nf = 0; nf < 2; nf++) {
                int col = wn * 16 + nf * 8 + 2 * tg;
                float2 v = make_float2(acc[mf][nf][half * 2], acc[mf][nf][half * 2 + 1]);
                *(float2*)&orow[col] = v;
            }
        }
    }
}

// ================= launch =================
extern "C" void kernel_launch(void* const* d_in, const int* in_sizes, int n_in,
                              void* d_out, int out_size) {
    const float* x  = (const float*)d_in[0];
    const float* gw = (const float*)d_in[1];
    const float* gp = (const float*)d_in[2];
    const float* up = (const float*)d_in[3];
    const float* dp = (const float*)d_in[4];
    float* y = (float*)d_out;

    int T = in_sizes[0] / HIDDEN;
    int nTot = T * HIDDEN;

    static bool attr_done = false;
    if (!attr_done) {
        cudaFuncSetAttribute(e1_kernel, cudaFuncAttributeMaxDynamicSharedMemorySize, E1_SMEM);
        cudaFuncSetAttribute(e2_kernel, cudaFuncAttributeMaxDynamicSharedMemorySize, E2_SMEM);
        attr_done = true;
    }

    prep_x_kernel<<<(nTot / 4 + 255) / 256, 256>>>(x, nTot);
    router_kernel<<<T, 128>>>(x, gw);
    build_kernel<<<1, NE>>>(T);

    dim3 g1(NE, (T + 63) / 64, INTER / 64);    // (32, 8, 12)
    e1_kernel<<<g1, 256, E1_SMEM>>>(gp, up);

    dim3 g2(NE, (T + 63) / 64, HIDDEN / 64);   // (32, 8, 32)
    e2_kernel<<<g2, 256, E2_SMEM>>>(dp);

    combine_kernel<<<T, 256>>>(y);
}